// round 1
// baseline (speedup 1.0000x reference)
#include <cuda_runtime.h>
#include <math.h>

// Problem constants
#define NV 16
#define NSAMP 8192          // BATCH*SEQ = 16*512
#define PPAIR 240

// ---------------- device scratch (no allocations allowed) ----------------
__device__ float g_avg[512 * 16];      // mean over batch: (SEQ, NV)
__device__ float g_pm[240];            // parent_mask [v][p] as 0/1
__device__ float g_hp[16];             // has_parents per v
__device__ float g_part[240 * 128];    // pair-score partial sums [pair][block]

// ---------------- Kernel A1: avg over batch ----------------
__global__ void k_avg(const float* __restrict__ data) {
    int a = blockIdx.x * 256 + threadIdx.x;   // 0..8191 -> (s,j)
    float s = 0.f;
#pragma unroll
    for (int b = 0; b < 16; b++) s += data[b * 8192 + a];
    g_avg[a] = s * (1.f / 16.f);
}

// ---------------- Kernel A2: cov -> corr -> MLP -> adj -> masks ----------------
__global__ void __launch_bounds__(1024) k_adj(
    const float* __restrict__ Ws1, const float* __restrict__ bs1,
    const float* __restrict__ Ws2, const float* __restrict__ bs2,
    const float* __restrict__ Ws3, const float* __restrict__ bs3,
    float* __restrict__ out_adj)
{
    __shared__ float av[8192];
    __shared__ float scratch[1024];
    __shared__ float cm[16];
    __shared__ float covs[256];
    __shared__ float corr_s[256];
    __shared__ float h1s[256];
    __shared__ float h2s[128];
    __shared__ float adj_s[256];
    __shared__ float pms[240];

    int tid = threadIdx.x;
    for (int i = tid; i < 8192; i += 1024) av[i] = g_avg[i];
    __syncthreads();

    // column means over SEQ=512
    if (tid < 512) {
        int j = tid & 15, part = tid >> 4;   // 32 parts x 16 rows
        float s = 0.f;
        for (int r = 0; r < 16; r++) s += av[(part * 16 + r) * 16 + j];
        scratch[tid] = s;
    }
    __syncthreads();
    if (tid < 16) {
        float s = 0.f;
        for (int part = 0; part < 32; part++) s += scratch[part * 16 + tid];
        cm[tid] = s * (1.f / 512.f);
    }
    __syncthreads();

    // cov[i][j] = sum_s (av[s][i]-cm[i])*(av[s][j]-cm[j]), 4 partials/pair
    {
        int pair = tid >> 2, q = tid & 3;
        int i = pair >> 4, j = pair & 15;
        float ci = cm[i], cj = cm[j];
        float s = 0.f;
        for (int r = q * 128; r < q * 128 + 128; r++)
            s += (av[r * 16 + i] - ci) * (av[r * 16 + j] - cj);
        scratch[tid] = s;
    }
    __syncthreads();
    if (tid < 256)
        covs[tid] = scratch[tid*4] + scratch[tid*4+1] + scratch[tid*4+2] + scratch[tid*4+3];
    __syncthreads();
    if (tid < 256) {
        int i = tid >> 4, j = tid & 15;
        float si = sqrtf(fmaxf(covs[i * 16 + i], 0.f));
        float sj = sqrtf(fmaxf(covs[j * 16 + j], 0.f));
        float denom = si * sj;
        float c = denom > 0.f ? covs[tid] / denom : 0.f;
        c = fabsf(c);
        if (i == j) c = 0.f;
        corr_s[tid] = c;
    }
    __syncthreads();

    // L1: (1,256) @ (256,256)
    {
        int o = tid & 255, q = tid >> 8;     // 4 partials
        float s = 0.f;
        for (int k = q * 64; k < q * 64 + 64; k++) s = fmaf(corr_s[k], Ws1[k * 256 + o], s);
        scratch[q * 256 + o] = s;
    }
    __syncthreads();
    if (tid < 256)
        h1s[tid] = fmaxf(scratch[tid] + scratch[256 + tid] + scratch[512 + tid] + scratch[768 + tid] + bs1[tid], 0.f);
    __syncthreads();

    // L2: (1,256) @ (256,128)
    {
        int o = tid & 127, q = tid >> 7;     // 8 partials
        float s = 0.f;
        for (int k = q * 32; k < q * 32 + 32; k++) s = fmaf(h1s[k], Ws2[k * 128 + o], s);
        scratch[q * 128 + o] = s;
    }
    __syncthreads();
    if (tid < 128) {
        float s = bs2[tid];
        for (int q = 0; q < 8; q++) s += scratch[q * 128 + tid];
        h2s[tid] = fmaxf(s, 0.f);
    }
    __syncthreads();

    // L3: (1,128) @ (128,256) -> sigmoid -> triu
    {
        int o = tid & 255, q = tid >> 8;     // 4 partials of 32
        float s = 0.f;
        for (int k = q * 32; k < q * 32 + 32; k++) s = fmaf(h2s[k], Ws3[k * 256 + o], s);
        scratch[q * 256 + o] = s;
    }
    __syncthreads();
    if (tid < 256) {
        float logit = scratch[tid] + scratch[256 + tid] + scratch[512 + tid] + scratch[768 + tid] + bs3[tid];
        float a = 1.f / (1.f + expf(-logit));
        int i = tid >> 4, j = tid & 15;
        float val = (j > i) ? a : 0.f;
        adj_s[tid] = val;
        out_adj[tid] = val;
    }
    __syncthreads();
    if (tid < 240) {
        int v = tid / 15, p = tid - v * 15;
        int g = p + (p >= v ? 1 : 0);
        float m = (adj_s[g * 16 + v] > 0.5f) ? 1.f : 0.f;
        pms[tid] = m;
        g_pm[tid] = m;
    }
    __syncthreads();
    if (tid < 16) {
        float s = 0.f;
        for (int p = 0; p < 15; p++) s += pms[tid * 15 + p];
        g_hp[tid] = (s > 0.f) ? 1.f : 0.f;
    }
}

// ---------------- Kernel B: mechanism MLP ----------------
// grid = (16 chunks, 16 vars), 256 threads (8 warps), warp does 8 samples/iter.
// smem layout (floats):
//   W1s [15*128]        @ 0
//   b1s [128]           @ 1920
//   W2t [64*132] (k-major, pad 132 -> conflict-free LDS.128) @ 2048
//   b2s [64]            @ 10496
//   W3s [64]            @ 10560
//   pms [16]            @ 10624
//   raw  [8w][8s][16]   @ 10640
//   inpm [8w][8s][16]   @ 11664
//   h1sh [8w][8s][128]  @ 12688
// total 20880 floats = 83520 bytes
__global__ void __launch_bounds__(256) k_mech(
    const float* __restrict__ data,
    const float* __restrict__ Wm1, const float* __restrict__ bm1,
    const float* __restrict__ Wm2, const float* __restrict__ bm2,
    const float* __restrict__ Wm3, const float* __restrict__ bm3,
    float* __restrict__ out_pred)
{
    extern __shared__ float sm[];
    const int v = blockIdx.y;
    float* W1s  = sm;
    float* b1s  = sm + 1920;
    float* W2t  = sm + 2048;
    float* b2s  = sm + 10496;
    float* W3s  = sm + 10560;
    float* pms  = sm + 10624;
    float* raw  = sm + 10640;
    float* inpm = sm + 11664;
    float* h1sh = sm + 12688;

    int tid = threadIdx.x;
    for (int t = tid; t < 1920; t += 256) W1s[t] = Wm1[v * 1920 + t];
    if (tid < 128) b1s[tid] = bm1[v * 128 + tid];
    for (int t = tid; t < 8192; t += 256) {
        int j = t >> 6, k = t & 63;
        W2t[k * 132 + j] = Wm2[v * 8192 + t];
    }
    if (tid < 64) { b2s[tid] = bm2[v * 64 + tid]; W3s[tid] = Wm3[v * 64 + tid]; }
    if (tid < 15) pms[tid] = g_pm[v * 15 + tid];
    float hp = g_hp[v];
    float b3 = bm3[v];
    __syncthreads();

    int w = tid >> 5, lane = tid & 31;
    float* rawW = raw  + w * 128;    // [s][16]
    float* inW  = inpm + w * 128;    // [s][16] (15 used)
    float* h1W  = h1sh + w * 1024;   // [s][128]

    for (int it = 0; it < 8; it++) {
        int base = blockIdx.x * 512 + w * 64 + it * 8;
        // load 8 sample rows (512B contiguous, fully coalesced)
        {
            int s = lane >> 2, q = lane & 3;
            float4 rv = *(const float4*)(data + (base + s) * 16 + q * 4);
            *(float4*)(rawW + s * 16 + q * 4) = rv;
        }
        __syncwarp();
        // masked, permuted inputs
        for (int t = lane; t < 120; t += 32) {
            int s = t / 15; int p = t - s * 15;
            inW[s * 16 + p] = rawW[s * 16 + p + (p >= v ? 1 : 0)] * pms[p];
        }
        __syncwarp();
        // h1: each lane owns 4 of 128 outputs for all 8 samples
        float4 acc[8];
        float4 b1v = *(float4*)(b1s + lane * 4);
#pragma unroll
        for (int s = 0; s < 8; s++) acc[s] = b1v;
#pragma unroll 5
        for (int p = 0; p < 15; p++) {
            float4 wv = *(float4*)(W1s + p * 128 + lane * 4);
#pragma unroll
            for (int s = 0; s < 8; s++) {
                float x = inW[s * 16 + p];
                acc[s].x = fmaf(wv.x, x, acc[s].x);
                acc[s].y = fmaf(wv.y, x, acc[s].y);
                acc[s].z = fmaf(wv.z, x, acc[s].z);
                acc[s].w = fmaf(wv.w, x, acc[s].w);
            }
        }
#pragma unroll
        for (int s = 0; s < 8; s++) {
            float4 r;
            r.x = fmaxf(acc[s].x, 0.f);
            r.y = fmaxf(acc[s].y, 0.f);
            r.z = fmaxf(acc[s].z, 0.f);
            r.w = fmaxf(acc[s].w, 0.f);
            *(float4*)(h1W + s * 128 + lane * 4) = r;
        }
        __syncwarp();
        // h2: lane owns k0=lane, k1=lane+32
        float a0[8], a1[8];
        float b20 = b2s[lane], b21 = b2s[lane + 32];
#pragma unroll
        for (int s = 0; s < 8; s++) { a0[s] = b20; a1[s] = b21; }
#pragma unroll 4
        for (int j4 = 0; j4 < 32; j4++) {
            float4 w0 = *(float4*)(W2t + lane * 132 + j4 * 4);
            float4 w1 = *(float4*)(W2t + (lane + 32) * 132 + j4 * 4);
#pragma unroll
            for (int s = 0; s < 8; s++) {
                float4 h4 = *(float4*)(h1W + s * 128 + j4 * 4);
                a0[s] = fmaf(w0.x, h4.x, a0[s]);
                a0[s] = fmaf(w0.y, h4.y, a0[s]);
                a0[s] = fmaf(w0.z, h4.z, a0[s]);
                a0[s] = fmaf(w0.w, h4.w, a0[s]);
                a1[s] = fmaf(w1.x, h4.x, a1[s]);
                a1[s] = fmaf(w1.y, h4.y, a1[s]);
                a1[s] = fmaf(w1.z, h4.z, a1[s]);
                a1[s] = fmaf(w1.w, h4.w, a1[s]);
            }
        }
        // mech = sum_k relu(h2)*W3 + b3 ; warp reduce per sample
        float w3a = W3s[lane], w3b = W3s[lane + 32];
#pragma unroll
        for (int s = 0; s < 8; s++) {
            float vs = fmaf(fmaxf(a0[s], 0.f), w3a, fmaxf(a1[s], 0.f) * w3b);
#pragma unroll
            for (int off = 16; off > 0; off >>= 1)
                vs += __shfl_xor_sync(0xffffffffu, vs, off);
            if (lane == 0) {
                float pred = (hp > 0.f) ? (vs + b3) : rawW[s * 16 + v];
                out_pred[(base + s) * 16 + v] = pred;
            }
        }
        __syncwarp();
    }
}

// ---------------- Kernel C: pair scorer (weights in registers) ----------------
// 128 blocks x 64 samples; thread p (<240) handles one pair across the chunk.
__global__ void __launch_bounds__(256) k_pairs(
    const float* __restrict__ data,
    const float* __restrict__ Wt1, const float* __restrict__ bt1,
    const float* __restrict__ Wt2, const float* __restrict__ bt2)
{
    __shared__ float rows[64 * 17];   // pad 17 -> conflict-free column reads
    int tid = threadIdx.x;
    int sbase = blockIdx.x * 64;
    for (int t = tid; t < 1024; t += 256) {
        int s = t >> 4, j = t & 15;
        rows[s * 17 + j] = data[(sbase + s) * 16 + j];
    }
    __syncthreads();
    if (tid < 240) {
        int p = tid;
        int pi = p / 15, r = p - pi * 15;
        int pj = r + (r >= pi ? 1 : 0);
        float4 w1a[8], w1b[8], bb[8], w2v[8];
#pragma unroll
        for (int q = 0; q < 8; q++) {
            w1a[q] = *(const float4*)(Wt1 + p * 64 + q * 4);
            w1b[q] = *(const float4*)(Wt1 + p * 64 + 32 + q * 4);
            bb[q]  = *(const float4*)(bt1 + p * 32 + q * 4);
            w2v[q] = *(const float4*)(Wt2 + p * 32 + q * 4);
        }
        float b2v = bt2[p];
        float accs = 0.f;
        for (int s = 0; s < 64; s++) {
            float xi = rows[s * 17 + pi], xj = rows[s * 17 + pj];
            float sv = b2v;
#pragma unroll
            for (int q = 0; q < 8; q++) {
                float hx = fmaf(xj, w1b[q].x, fmaf(xi, w1a[q].x, bb[q].x));
                float hy = fmaf(xj, w1b[q].y, fmaf(xi, w1a[q].y, bb[q].y));
                float hz = fmaf(xj, w1b[q].z, fmaf(xi, w1a[q].z, bb[q].z));
                float hw = fmaf(xj, w1b[q].w, fmaf(xi, w1a[q].w, bb[q].w));
                sv = fmaf(fmaxf(hx, 0.f), w2v[q].x, sv);
                sv = fmaf(fmaxf(hy, 0.f), w2v[q].y, sv);
                sv = fmaf(fmaxf(hz, 0.f), w2v[q].z, sv);
                sv = fmaf(fmaxf(hw, 0.f), w2v[q].w, sv);
            }
            accs += __fdividef(1.f, 1.f + __expf(-sv));
        }
        g_part[p * 128 + blockIdx.x] = accs;   // deterministic (no atomics)
    }
}

// ---------------- Kernel D: finalize scores ----------------
__global__ void k_fin(float* __restrict__ out_scores) {
    int t = threadIdx.x;   // 256
    int i = t >> 4, j = t & 15;
    float val = 0.f;
    if (i != j) {
        int p = i * 15 + (j > i ? j - 1 : j);
        float s = 0.f;
        for (int b = 0; b < 128; b++) s += g_part[p * 128 + b];
        val = s * (1.f / 8192.f);
    }
    out_scores[t] = val;
}

// ---------------- launch ----------------
extern "C" void kernel_launch(void* const* d_in, const int* in_sizes, int n_in,
                              void* d_out, int out_size) {
    const float* data = (const float*)d_in[0];
    const float* Ws1 = (const float*)d_in[1];
    const float* bs1 = (const float*)d_in[2];
    const float* Ws2 = (const float*)d_in[3];
    const float* bs2 = (const float*)d_in[4];
    const float* Ws3 = (const float*)d_in[5];
    const float* bs3 = (const float*)d_in[6];
    const float* Wm1 = (const float*)d_in[7];
    const float* bm1 = (const float*)d_in[8];
    const float* Wm2 = (const float*)d_in[9];
    const float* bm2 = (const float*)d_in[10];
    const float* Wm3 = (const float*)d_in[11];
    const float* bm3 = (const float*)d_in[12];
    const float* Wt1 = (const float*)d_in[13];
    const float* bt1 = (const float*)d_in[14];
    const float* Wt2 = (const float*)d_in[15];
    const float* bt2 = (const float*)d_in[16];

    float* out = (float*)d_out;
    float* out_adj    = out;                 // 256
    float* out_pred   = out + 256;           // 131072
    float* out_scores = out + 256 + 131072;  // 256

    cudaFuncSetAttribute(k_mech, cudaFuncAttributeMaxDynamicSharedMemorySize, 83520);

    k_avg<<<32, 256>>>(data);
    k_adj<<<1, 1024>>>(Ws1, bs1, Ws2, bs2, Ws3, bs3, out_adj);
    k_mech<<<dim3(16, 16), 256, 83520>>>(data, Wm1, bm1, Wm2, bm2, Wm3, bm3, out_pred);
    k_pairs<<<128, 256>>>(data, Wt1, bt1, Wt2, bt2);
    k_fin<<<1, 256>>>(out_scores);
}